// round 13
// baseline (speedup 1.0000x reference)
#include <cuda_runtime.h>
#include <cuda_fp16.h>
#include <math.h>
#include <stdint.h>

#define B_  2
#define L_  8192
#define H_  16
#define D_  64
#define C_  1024
#define BK  64
#define LOG2E 1.4426950408889634f

__device__ float g_invf[32];
__device__ float g_cos[L_ * 32];
__device__ float g_sin[L_ * 32];

// fragment-ready scratch (u64 units): K hi/lo fp16, V single fp16
__device__ uint64_t g_KfH[4194304];
__device__ uint64_t g_KfL[4194304];
__device__ uint64_t g_Vf [4194304];

// 32 threads: inv_freq = fp32(1/10000^(j/32)) via double pow (same chain as reference)
__global__ void invf_k() {
    int j = threadIdx.x;
    if (j < 32) g_invf[j] = (float)(1.0 / pow(10000.0, (double)j / 32.0));
}

// cos/sin of the fp32 angle: double RANGE-REDUCTION only, then fp32 sincosf
__global__ void rope_table_k(const int* __restrict__ startp) {
    int i = blockIdx.x * blockDim.x + threadIdx.x;
    if (i >= L_ * 32) return;
    int pos = *startp + (i >> 5);
    int j = i & 31;
    float ang = (float)pos * g_invf[j];
    double td = (double)ang;
    double kd = rint(td * 0.15915494309189535);
    float r = (float)(td - kd * 6.283185307179586);
    float s, c;
    sincosf(r, &s, &c);
    g_cos[i] = c;
    g_sin[i] = s;
}

// ---------------- helpers ----------------
__device__ __forceinline__ uint32_t smem_u32(const void* p) {
    uint32_t a;
    asm("{ .reg .u64 t; cvta.to.shared.u64 t, %1; cvt.u32.u64 %0, t; }" : "=r"(a) : "l"(p));
    return a;
}
__device__ __forceinline__ float ex2f(float x) {
    float y; asm("ex2.approx.ftz.f32 %0, %1;" : "=f"(y) : "f"(x)); return y;
}
__device__ __forceinline__ void lds64(uint32_t& x, uint32_t& y, uint32_t a) {
    asm volatile("ld.shared.v2.b32 {%0,%1}, [%2];" : "=r"(x), "=r"(y) : "r"(a));
}
__device__ __forceinline__ void cpa16(uint32_t s, const uint64_t* g) {
    asm volatile("cp.async.cg.shared.global [%0], [%1], 16;" :: "r"(s), "l"(g));
}
#define CP_COMMIT() asm volatile("cp.async.commit_group;" ::: "memory")
#define CP_WAIT0()  asm volatile("cp.async.wait_group 0;" ::: "memory")
__device__ __forceinline__ void mma_f16(float* c, const uint32_t* a, uint32_t b0, uint32_t b1) {
    asm volatile(
        "mma.sync.aligned.m16n8k16.row.col.f32.f16.f16.f32 "
        "{%0,%1,%2,%3}, {%4,%5,%6,%7}, {%8,%9}, {%0,%1,%2,%3};"
        : "+f"(c[0]), "+f"(c[1]), "+f"(c[2]), "+f"(c[3])
        : "r"(a[0]), "r"(a[1]), "r"(a[2]), "r"(a[3]), "r"(b0), "r"(b1));
}
__device__ __forceinline__ uint32_t pack_h(float x0, float x1) {
    __half2 h = __floats2half2_rn(x0, x1);
    return *reinterpret_cast<uint32_t*>(&h);
}
__device__ __forceinline__ void pack_hilo_h(float x0, float x1, uint32_t& hi, uint32_t& lo) {
    __half2 h = __floats2half2_rn(x0, x1);
    float2 hf = __half22float2(h);
    __half2 l = __floats2half2_rn(x0 - hf.x, x1 - hf.y);
    hi = *reinterpret_cast<uint32_t*>(&h);
    lo = *reinterpret_cast<uint32_t*>(&l);
}

// ---------------- fused prep: K -> RoPE'd fp16 hi/lo frags; V -> transposed fp16 frags --
__global__ void __launch_bounds__(256) prep_kv(const float* __restrict__ k,
                                               const float* __restrict__ v) {
    __shared__ float tile[64][65];
    if (blockIdx.x < 8192) {
        // ----- K part -----
        uint32_t g = blockIdx.x * 256 + threadIdx.x;
        int lb = g & 3, la = (g >> 2) & 7, t01 = (g >> 5) & 1, m = (g >> 6) & 1023;
        int sc = g >> 16;
        int b = sc >> 4, h = sc & 15;
        int l = 8 * m + la;
        const float* gk = k + (((long)b * L_ + l) * H_ + h) * D_;
        int d0 = 16 * t01 + 2 * lb;
        float2 x0 = *(const float2*)(gk + d0);
        float2 x1 = *(const float2*)(gk + d0 + 8);
        float2 y0 = *(const float2*)(gk + d0 + 32);
        float2 y1 = *(const float2*)(gk + d0 + 40);
        float2 c0 = *(const float2*)(g_cos + l * 32 + d0);
        float2 c1 = *(const float2*)(g_cos + l * 32 + d0 + 8);
        float2 s0 = *(const float2*)(g_sin + l * 32 + d0);
        float2 s1 = *(const float2*)(g_sin + l * 32 + d0 + 8);
        uint32_t hA, lA, hB, lB;
        pack_hilo_h(x0.x*c0.x - y0.x*s0.x, x0.y*c0.y - y0.y*s0.y, hA, lA);
        pack_hilo_h(x1.x*c1.x - y1.x*s1.x, x1.y*c1.y - y1.y*s1.y, hB, lB);
        uint64_t loHi = (uint64_t)hA | ((uint64_t)hB << 32);
        uint64_t loLo = (uint64_t)lA | ((uint64_t)lB << 32);
        pack_hilo_h(y0.x*c0.x + x0.x*s0.x, y0.y*c0.y + x0.y*s0.y, hA, lA);
        pack_hilo_h(y1.x*c1.x + x1.x*s1.x, y1.y*c1.y + x1.y*s1.y, hB, lB);
        uint64_t hiHi = (uint64_t)hA | ((uint64_t)hB << 32);
        uint64_t hiLo = (uint64_t)lA | ((uint64_t)lB << 32);
        uint32_t base = ((uint32_t)sc * 1024 + m) * 128 + la * 4 + lb;
        g_KfH[base + t01 * 32]       = loHi;
        g_KfL[base + t01 * 32]       = loLo;
        g_KfH[base + (t01 + 2) * 32] = hiHi;
        g_KfL[base + (t01 + 2) * 32] = hiLo;
    } else {
        // ----- V part (smem transpose; scalar smem stores: 65-f rows not 16B aligned) ----
        const int blk = blockIdx.x - 8192;       // sc*128 + gt
        const int sc = blk >> 7, gt = blk & 127;
        const int b = sc >> 4, h = sc & 15;
        const int t = threadIdx.x;
        {
            const int r = t >> 2, dseg = (t & 3) * 16;
            const float* gv = v + (((long)b * L_ + (gt * 64 + r)) * H_ + h) * D_ + dseg;
            float a0[4], a1[4], a2[4], a3[4];
            *(float4*)a0 = *(const float4*)(gv);
            *(float4*)a1 = *(const float4*)(gv + 4);
            *(float4*)a2 = *(const float4*)(gv + 8);
            *(float4*)a3 = *(const float4*)(gv + 12);
            #pragma unroll
            for (int i = 0; i < 4; i++) {
                tile[r][dseg + i]      = a0[i];
                tile[r][dseg + 4 + i]  = a1[i];
                tile[r][dseg + 8 + i]  = a2[i];
                tile[r][dseg + 12 + i] = a3[i];
            }
        }
        __syncthreads();
        const int lb = t & 3, d = (t >> 2) & 63;
        uint64_t* outp = g_Vf + ((uint32_t)(sc * 128 + gt)) * 1024 + d * 4 + lb;
        #pragma unroll
        for (int t2 = 0; t2 < 4; t2++) {
            int r0 = t2 * 16 + 2 * lb;
            uint32_t w0 = pack_h(tile[r0][d],     tile[r0 + 1][d]);
            uint32_t w1 = pack_h(tile[r0 + 8][d], tile[r0 + 9][d]);
            outp[t2 * 256] = (uint64_t)w0 | ((uint64_t)w1 << 32);
        }
    }
}

// smem per buffer: KH 8KB | KL 8KB | V 8KB = 24KB; double buffered = 48KB
#define BUFB 24576
#define P_KH 0
#define P_KL 8192
#define P_V  16384

// ---------------- main: 8 warps, M=16/warp, fp16 4-pass, 16 warps/SM ----------------
__global__ void __launch_bounds__(256, 2)
attn_k(const float* __restrict__ q, float* __restrict__ out) {
    extern __shared__ __align__(16) char smc[];
    const uint32_t sb = smem_u32(smc);
    const int tid = threadIdx.x, w = tid >> 5, lane = tid & 31;
    const int qt = 7 - blockIdx.x;            // heavy CTAs first
    const int n  = blockIdx.y >> 4, h = blockIdx.y & 15, b = blockIdx.z;
    const int sc = b * 16 + h;
    const int qbase = qt * 128;
    const int la = lane >> 2, lb = lane & 3;
    const int nkt = 2 * qt + 2;

    const uint64_t* pKH = g_KfH + ((uint32_t)sc * 1024 + n * 128) * 128;
    const uint64_t* pKL = g_KfL + ((uint32_t)sc * 1024 + n * 128) * 128;
    const uint64_t* pV  = g_Vf  + ((uint32_t)sc * 128  + n * 16 ) * 1024;

    // kick off copy of tile 0 (256 threads: 2 x 16B per plane each)
    {
        uint32_t dst = sb + tid * 16;
        const uint32_t o2 = (uint32_t)tid * 2;
        cpa16(dst + P_KH,        pKH + o2);
        cpa16(dst + P_KH + 4096, pKH + o2 + 512);
        cpa16(dst + P_KL,        pKL + o2);
        cpa16(dst + P_KL + 4096, pKL + o2 + 512);
        cpa16(dst + P_V,         pV  + o2);
        cpa16(dst + P_V  + 4096, pV  + o2 + 512);
        CP_COMMIT();
    }

    // ---------- Q: load + RoPE(+log2e) + fp16 split -> A fragments (M=16) ----------
    uint32_t Qhi[4][4], Qlo[4][4];
    {
        const int bq = lb * 2;
        float rot[2][4][4];
        #pragma unroll
        for (int r = 0; r < 2; r++) {
            int m  = 16 * w + la + 8 * r;
            int lq = n * C_ + qbase + m;
            const float* gq = q + (((long)b * L_ + lq) * H_ + h) * D_;
            const float* gc = g_cos + lq * 32;
            const float* gs = g_sin + lq * 32;
            float xv[4][4], cs[2][4], sn[2][4];
            #pragma unroll
            for (int t = 0; t < 4; t++) {
                float2 u0 = *(const float2*)(gq + 16 * t + bq);
                float2 u1 = *(const float2*)(gq + 16 * t + bq + 8);
                xv[t][0] = u0.x; xv[t][1] = u0.y; xv[t][2] = u1.x; xv[t][3] = u1.y;
            }
            #pragma unroll
            for (int t = 0; t < 2; t++) {
                float2 c0 = *(const float2*)(gc + 16 * t + bq);
                float2 c1 = *(const float2*)(gc + 16 * t + bq + 8);
                cs[t][0] = c0.x; cs[t][1] = c0.y; cs[t][2] = c1.x; cs[t][3] = c1.y;
                float2 s0 = *(const float2*)(gs + 16 * t + bq);
                float2 s1 = *(const float2*)(gs + 16 * t + bq + 8);
                sn[t][0] = s0.x; sn[t][1] = s0.y; sn[t][2] = s1.x; sn[t][3] = s1.y;
            }
            #pragma unroll
            for (int t = 0; t < 2; t++)
                #pragma unroll
                for (int i = 0; i < 4; i++) {
                    rot[r][t][i]   = (xv[t][i] * cs[t][i] - xv[t+2][i] * sn[t][i]) * LOG2E;
                    rot[r][t+2][i] = (xv[t+2][i] * cs[t][i] + xv[t][i] * sn[t][i]) * LOG2E;
                }
        }
        #pragma unroll
        for (int t = 0; t < 4; t++) {
            pack_hilo_h(rot[0][t][0], rot[0][t][1], Qhi[t][0], Qlo[t][0]);
            pack_hilo_h(rot[1][t][0], rot[1][t][1], Qhi[t][1], Qlo[t][1]);
            pack_hilo_h(rot[0][t][2], rot[0][t][3], Qhi[t][2], Qlo[t][2]);
            pack_hilo_h(rot[1][t][2], rot[1][t][3], Qhi[t][3], Qlo[t][3]);
        }
    }

    float o[8][4];
    #pragma unroll
    for (int j = 0; j < 8; j++)
        #pragma unroll
        for (int i = 0; i < 4; i++) o[j][i] = 0.f;
    float ls[2] = {0.f, 0.f};
    float m_[2] = {-1e30f, -1e30f};

    const int row0 = qbase + 16 * w + la;
    const int row1 = row0 + 8;

    for (int kt = 0; kt < nkt; kt++) {
        const int kbase = kt * BK;
        CP_WAIT0();
        __syncthreads();
        if (kt + 1 < nkt) {
            uint32_t dst = sb + ((kt + 1) & 1) * BUFB + tid * 16;
            const uint32_t o2 = (uint32_t)(kt + 1) * 1024 + (uint32_t)tid * 2;
            cpa16(dst + P_KH,        pKH + o2);
            cpa16(dst + P_KH + 4096, pKH + o2 + 512);
            cpa16(dst + P_KL,        pKL + o2);
            cpa16(dst + P_KL + 4096, pKL + o2 + 512);
            cpa16(dst + P_V,         pV  + o2);
            cpa16(dst + P_V  + 4096, pV  + o2 + 512);
            CP_COMMIT();
        }
        const uint32_t KB = sb + (kt & 1) * BUFB;
        const uint32_t fo = (uint32_t)(la * 32 + lb * 8);

        // ---------- S = Q @ K^T (3-pass fp16 split, j-pair interleaved) ----------
        float c[8][4];
        #pragma unroll
        for (int j = 0; j < 8; j++)
            #pragma unroll
            for (int i = 0; i < 4; i++) c[j][i] = 0.f;

        #pragma unroll
        for (int t = 0; t < 4; t++) {
            #pragma unroll
            for (int j = 0; j < 8; j += 2) {
                uint32_t a0 = KB + P_KH + (uint32_t)j * 1024 + (uint32_t)t * 256 + fo;
                uint32_t bh0a, bh1a, bh0b, bh1b, bl0a, bl1a, bl0b, bl1b;
                lds64(bh0a, bh1a, a0);
                lds64(bh0b, bh1b, a0 + 1024);
                lds64(bl0a, bl1a, a0 + (P_KL - P_KH));
                lds64(bl0b, bl1b, a0 + (P_KL - P_KH) + 1024);
                mma_f16(c[j],   Qhi[t], bh0a, bh1a);
                mma_f16(c[j+1], Qhi[t], bh0b, bh1b);
                mma_f16(c[j],   Qlo[t], bh0a, bh1a);
                mma_f16(c[j+1], Qlo[t], bh0b, bh1b);
                mma_f16(c[j],   Qhi[t], bl0a, bl1a);
                mma_f16(c[j+1], Qhi[t], bl0b, bl1b);
            }
        }

        // ---------- mask ----------
        if (kbase + BK > row0) {
            #pragma unroll
            for (int j = 0; j < 8; j++) {
                int col = kbase + 8 * j + lb * 2;
                if (col     > row0) c[j][0] = -1e30f;
                if (col + 1 > row0) c[j][1] = -1e30f;
                if (col     > row1) c[j][2] = -1e30f;
                if (col + 1 > row1) c[j][3] = -1e30f;
            }
        }

        // ---------- running max update + ls rescale ----------
        float scl[2];
        #pragma unroll
        for (int rh = 0; rh < 2; rh++) {
            float mx = -1e30f;
            #pragma unroll
            for (int j = 0; j < 8; j++)
                mx = fmaxf(mx, fmaxf(c[j][2*rh], c[j][2*rh+1]));
            mx = fmaxf(mx, __shfl_xor_sync(0xffffffffu, mx, 1));
            mx = fmaxf(mx, __shfl_xor_sync(0xffffffffu, mx, 2));
            float mn = fmaxf(m_[rh], mx);
            float s = ex2f(m_[rh] - mn);
            m_[rh] = mn;
            scl[rh] = s;
            ls[rh] *= s;
        }
        bool need = (scl[0] != 1.f) | (scl[1] != 1.f);
        if (__any_sync(0xffffffffu, need)) {
            #pragma unroll
            for (int j = 0; j < 8; j++) {
                o[j][0] *= scl[0]; o[j][1] *= scl[0];
                o[j][2] *= scl[1]; o[j][3] *= scl[1];
            }
        }

        // ---------- exp2 + pack P (single fp16 plane, in [0,1]) ----------
        uint32_t Phi[4][4];
        #pragma unroll
        for (int j = 0; j < 8; j++) {
            float p0 = ex2f(c[j][0] - m_[0]);
            float p1 = ex2f(c[j][1] - m_[0]);
            float p2 = ex2f(c[j][2] - m_[1]);
            float p3 = ex2f(c[j][3] - m_[1]);
            ls[0] += p0 + p1; ls[1] += p2 + p3;
            int t = j >> 1, off = (j & 1) ? 2 : 0;
            Phi[t][off]     = pack_h(p0, p1);
            Phi[t][off + 1] = pack_h(p2, p3);
        }

        // ---------- O += P @ V (single pass, j-pair interleaved) ----------
        #pragma unroll
        for (int t = 0; t < 4; t++) {
            #pragma unroll
            for (int j = 0; j < 8; j += 2) {
                uint32_t a0 = KB + P_V + (uint32_t)t * 2048 + (uint32_t)j * 256 + fo;
                uint32_t va0, va1, vb0, vb1;
                lds64(va0, va1, a0);
                lds64(vb0, vb1, a0 + 256);
                mma_f16(o[j],   Phi[t], va0, va1);
                mma_f16(o[j+1], Phi[t], vb0, vb1);
            }
        }
    }

    // ---------- normalize + store ----------
    #pragma unroll
    for (int i = 0; i < 2; i++) {
        ls[i] += __shfl_xor_sync(0xffffffffu, ls[i], 1);
        ls[i] += __shfl_xor_sync(0xffffffffu, ls[i], 2);
    }
    {
        float inv0 = 1.0f / ls[0], inv1 = 1.0f / ls[1];
        const int lq0 = n * C_ + row0, lq1 = n * C_ + row1;
        float* g0 = out + (((long)b * L_ + lq0) * H_ + h) * D_;
        float* g1 = out + (((long)b * L_ + lq1) * H_ + h) * D_;
        #pragma unroll
        for (int j = 0; j < 8; j++) {
            int d = 8 * j + lb * 2;
            *(float2*)(g0 + d) = make_float2(o[j][0] * inv0, o[j][1] * inv0);
            *(float2*)(g1 + d) = make_float2(o[j][2] * inv1, o[j][3] * inv1);
        }
    }
}

extern "C" void kernel_launch(void* const* d_in, const int* in_sizes, int n_in,
                              void* d_out, int out_size) {
    const float* q = (const float*)d_in[0];
    const float* k = (const float*)d_in[1];
    const float* v = (const float*)d_in[2];
    const int* st  = (const int*)d_in[3];
    float* out     = (float*)d_out;

    cudaFuncSetAttribute(attn_k, cudaFuncAttributeMaxDynamicSharedMemorySize, 2 * BUFB);

    invf_k<<<1, 32>>>();
    rope_table_k<<<(L_ * 32 + 255) / 256, 256>>>(st);
    prep_kv<<<8192 + 4096, 256>>>(k, v);
    attn_k<<<dim3(8, (L_ / C_) * H_, B_), 256, 2 * BUFB>>>(q, out);
}

// round 14
// speedup vs baseline: 1.0509x; 1.0509x over previous
#include <cuda_runtime.h>
#include <cuda_fp16.h>
#include <math.h>
#include <stdint.h>

#define B_  2
#define L_  8192
#define H_  16
#define D_  64
#define C_  1024
#define BK  64
#define LOG2E 1.4426950408889634f

__device__ float g_invf[32];
__device__ float g_cos[L_ * 32];
__device__ float g_sin[L_ * 32];

// fragment-ready scratch (u64 units): K hi/lo fp16, V single fp16
__device__ uint64_t g_KfH[4194304];
__device__ uint64_t g_KfL[4194304];
__device__ uint64_t g_Vf [4194304];

__global__ void invf_k() {
    int j = threadIdx.x;
    if (j < 32) g_invf[j] = (float)(1.0 / pow(10000.0, (double)j / 32.0));
}

__global__ void rope_table_k(const int* __restrict__ startp) {
    int i = blockIdx.x * blockDim.x + threadIdx.x;
    if (i >= L_ * 32) return;
    int pos = *startp + (i >> 5);
    int j = i & 31;
    float ang = (float)pos * g_invf[j];
    double td = (double)ang;
    double kd = rint(td * 0.15915494309189535);
    float r = (float)(td - kd * 6.283185307179586);
    float s, c;
    sincosf(r, &s, &c);
    g_cos[i] = c;
    g_sin[i] = s;
}

// ---------------- helpers ----------------
__device__ __forceinline__ uint32_t smem_u32(const void* p) {
    uint32_t a;
    asm("{ .reg .u64 t; cvta.to.shared.u64 t, %1; cvt.u32.u64 %0, t; }" : "=r"(a) : "l"(p));
    return a;
}
__device__ __forceinline__ float ex2f(float x) {
    float y; asm("ex2.approx.ftz.f32 %0, %1;" : "=f"(y) : "f"(x)); return y;
}
__device__ __forceinline__ void lds64(uint32_t& x, uint32_t& y, uint32_t a) {
    asm volatile("ld.shared.v2.b32 {%0,%1}, [%2];" : "=r"(x), "=r"(y) : "r"(a));
}
__device__ __forceinline__ void cpa16(uint32_t s, const uint64_t* g) {
    asm volatile("cp.async.cg.shared.global [%0], [%1], 16;" :: "r"(s), "l"(g));
}
#define CP_COMMIT() asm volatile("cp.async.commit_group;" ::: "memory")
#define CP_WAIT0()  asm volatile("cp.async.wait_group 0;" ::: "memory")
__device__ __forceinline__ void mma_f16(float* c, const uint32_t* a, uint32_t b0, uint32_t b1) {
    asm volatile(
        "mma.sync.aligned.m16n8k16.row.col.f32.f16.f16.f32 "
        "{%0,%1,%2,%3}, {%4,%5,%6,%7}, {%8,%9}, {%0,%1,%2,%3};"
        : "+f"(c[0]), "+f"(c[1]), "+f"(c[2]), "+f"(c[3])
        : "r"(a[0]), "r"(a[1]), "r"(a[2]), "r"(a[3]), "r"(b0), "r"(b1));
}
__device__ __forceinline__ uint32_t pack_h(float x0, float x1) {
    __half2 h = __floats2half2_rn(x0, x1);
    return *reinterpret_cast<uint32_t*>(&h);
}
__device__ __forceinline__ void pack_hilo_h(float x0, float x1, uint32_t& hi, uint32_t& lo) {
    __half2 h = __floats2half2_rn(x0, x1);
    float2 hf = __half22float2(h);
    __half2 l = __floats2half2_rn(x0 - hf.x, x1 - hf.y);
    hi = *reinterpret_cast<uint32_t*>(&h);
    lo = *reinterpret_cast<uint32_t*>(&l);
}

// ---------------- fused prep: K -> RoPE'd fp16 hi/lo frags; V -> transposed fp16 frags --
__global__ void __launch_bounds__(256) prep_kv(const float* __restrict__ k,
                                               const float* __restrict__ v) {
    __shared__ float tile[64][65];
    if (blockIdx.x < 8192) {
        uint32_t g = blockIdx.x * 256 + threadIdx.x;
        int lb = g & 3, la = (g >> 2) & 7, t01 = (g >> 5) & 1, m = (g >> 6) & 1023;
        int sc = g >> 16;
        int b = sc >> 4, h = sc & 15;
        int l = 8 * m + la;
        const float* gk = k + (((long)b * L_ + l) * H_ + h) * D_;
        int d0 = 16 * t01 + 2 * lb;
        float2 x0 = *(const float2*)(gk + d0);
        float2 x1 = *(const float2*)(gk + d0 + 8);
        float2 y0 = *(const float2*)(gk + d0 + 32);
        float2 y1 = *(const float2*)(gk + d0 + 40);
        float2 c0 = *(const float2*)(g_cos + l * 32 + d0);
        float2 c1 = *(const float2*)(g_cos + l * 32 + d0 + 8);
        float2 s0 = *(const float2*)(g_sin + l * 32 + d0);
        float2 s1 = *(const float2*)(g_sin + l * 32 + d0 + 8);
        uint32_t hA, lA, hB, lB;
        pack_hilo_h(x0.x*c0.x - y0.x*s0.x, x0.y*c0.y - y0.y*s0.y, hA, lA);
        pack_hilo_h(x1.x*c1.x - y1.x*s1.x, x1.y*c1.y - y1.y*s1.y, hB, lB);
        uint64_t loHi = (uint64_t)hA | ((uint64_t)hB << 32);
        uint64_t loLo = (uint64_t)lA | ((uint64_t)lB << 32);
        pack_hilo_h(y0.x*c0.x + x0.x*s0.x, y0.y*c0.y + x0.y*s0.y, hA, lA);
        pack_hilo_h(y1.x*c1.x + x1.x*s1.x, y1.y*c1.y + x1.y*s1.y, hB, lB);
        uint64_t hiHi = (uint64_t)hA | ((uint64_t)hB << 32);
        uint64_t hiLo = (uint64_t)lA | ((uint64_t)lB << 32);
        uint32_t base = ((uint32_t)sc * 1024 + m) * 128 + la * 4 + lb;
        g_KfH[base + t01 * 32]       = loHi;
        g_KfL[base + t01 * 32]       = loLo;
        g_KfH[base + (t01 + 2) * 32] = hiHi;
        g_KfL[base + (t01 + 2) * 32] = hiLo;
    } else {
        const int blk = blockIdx.x - 8192;       // sc*128 + gt
        const int sc = blk >> 7, gt = blk & 127;
        const int b = sc >> 4, h = sc & 15;
        const int t = threadIdx.x;
        {
            const int r = t >> 2, dseg = (t & 3) * 16;
            const float* gv = v + (((long)b * L_ + (gt * 64 + r)) * H_ + h) * D_ + dseg;
            float a0[4], a1[4], a2[4], a3[4];
            *(float4*)a0 = *(const float4*)(gv);
            *(float4*)a1 = *(const float4*)(gv + 4);
            *(float4*)a2 = *(const float4*)(gv + 8);
            *(float4*)a3 = *(const float4*)(gv + 12);
            #pragma unroll
            for (int i = 0; i < 4; i++) {
                tile[r][dseg + i]      = a0[i];
                tile[r][dseg + 4 + i]  = a1[i];
                tile[r][dseg + 8 + i]  = a2[i];
                tile[r][dseg + 12 + i] = a3[i];
            }
        }
        __syncthreads();
        const int lb = t & 3, d = (t >> 2) & 63;
        uint64_t* outp = g_Vf + ((uint32_t)(sc * 128 + gt)) * 1024 + d * 4 + lb;
        #pragma unroll
        for (int t2 = 0; t2 < 4; t2++) {
            int r0 = t2 * 16 + 2 * lb;
            uint32_t w0 = pack_h(tile[r0][d],     tile[r0 + 1][d]);
            uint32_t w1 = pack_h(tile[r0 + 8][d], tile[r0 + 9][d]);
            outp[t2 * 256] = (uint64_t)w0 | ((uint64_t)w1 << 32);
        }
    }
}

// smem per buffer: KH 8KB | KL 8KB | V 8KB = 24KB; double buffered = 48KB
#define BUFB 24576
#define P_KH 0
#define P_KL 8192
#define P_V  16384

// ------- main: 4 warps, M=16/warp (64-row CTAs), distance-8 mma schedule -------
__global__ void __launch_bounds__(128, 2)
attn_k(const float* __restrict__ q, float* __restrict__ out) {
    extern __shared__ __align__(16) char smc[];
    const uint32_t sb = smem_u32(smc);
    const int tid = threadIdx.x, w = tid >> 5, lane = tid & 31;
    const int qt2 = 15 - blockIdx.x;          // heavy CTAs first; 64-row q tile
    const int n  = blockIdx.y >> 4, h = blockIdx.y & 15, b = blockIdx.z;
    const int sc = b * 16 + h;
    const int qbase = qt2 * 64;
    const int la = lane >> 2, lb = lane & 3;
    const int nkt = qt2 + 1;

    const uint64_t* pKH = g_KfH + ((uint32_t)sc * 1024 + n * 128) * 128;
    const uint64_t* pKL = g_KfL + ((uint32_t)sc * 1024 + n * 128) * 128;
    const uint64_t* pV  = g_Vf  + ((uint32_t)sc * 128  + n * 16 ) * 1024;

    // kick off copy of tile 0 (128 threads x 4 x 16B per plane)
    {
        uint32_t dst = sb + tid * 16;
        const uint32_t o2 = (uint32_t)tid * 2;
        #pragma unroll
        for (int i = 0; i < 4; i++) {
            cpa16(dst + P_KH + i * 2048, pKH + o2 + i * 256);
            cpa16(dst + P_KL + i * 2048, pKL + o2 + i * 256);
            cpa16(dst + P_V  + i * 2048, pV  + o2 + i * 256);
        }
        CP_COMMIT();
    }

    // ---------- Q: load + RoPE(+log2e) + fp16 split -> A fragments (M=16) ----------
    uint32_t Qhi[4][4], Qlo[4][4];
    {
        const int bq = lb * 2;
        float rot[2][4][4];
        #pragma unroll
        for (int r = 0; r < 2; r++) {
            int m  = 16 * w + la + 8 * r;
            int lq = n * C_ + qbase + m;
            const float* gq = q + (((long)b * L_ + lq) * H_ + h) * D_;
            const float* gc = g_cos + lq * 32;
            const float* gs = g_sin + lq * 32;
            float xv[4][4], cs[2][4], sn[2][4];
            #pragma unroll
            for (int t = 0; t < 4; t++) {
                float2 u0 = *(const float2*)(gq + 16 * t + bq);
                float2 u1 = *(const float2*)(gq + 16 * t + bq + 8);
                xv[t][0] = u0.x; xv[t][1] = u0.y; xv[t][2] = u1.x; xv[t][3] = u1.y;
            }
            #pragma unroll
            for (int t = 0; t < 2; t++) {
                float2 c0 = *(const float2*)(gc + 16 * t + bq);
                float2 c1 = *(const float2*)(gc + 16 * t + bq + 8);
                cs[t][0] = c0.x; cs[t][1] = c0.y; cs[t][2] = c1.x; cs[t][3] = c1.y;
                float2 s0 = *(const float2*)(gs + 16 * t + bq);
                float2 s1 = *(const float2*)(gs + 16 * t + bq + 8);
                sn[t][0] = s0.x; sn[t][1] = s0.y; sn[t][2] = s1.x; sn[t][3] = s1.y;
            }
            #pragma unroll
            for (int t = 0; t < 2; t++)
                #pragma unroll
                for (int i = 0; i < 4; i++) {
                    rot[r][t][i]   = (xv[t][i] * cs[t][i] - xv[t+2][i] * sn[t][i]) * LOG2E;
                    rot[r][t+2][i] = (xv[t+2][i] * cs[t][i] + xv[t][i] * sn[t][i]) * LOG2E;
                }
        }
        #pragma unroll
        for (int t = 0; t < 4; t++) {
            pack_hilo_h(rot[0][t][0], rot[0][t][1], Qhi[t][0], Qlo[t][0]);
            pack_hilo_h(rot[1][t][0], rot[1][t][1], Qhi[t][1], Qlo[t][1]);
            pack_hilo_h(rot[0][t][2], rot[0][t][3], Qhi[t][2], Qlo[t][2]);
            pack_hilo_h(rot[1][t][2], rot[1][t][3], Qhi[t][3], Qlo[t][3]);
        }
    }

    float o[8][4];
    #pragma unroll
    for (int j = 0; j < 8; j++)
        #pragma unroll
        for (int i = 0; i < 4; i++) o[j][i] = 0.f;
    float ls[2] = {0.f, 0.f};
    float m_[2] = {-1e30f, -1e30f};

    const int row0 = qbase + 16 * w + la;
    const int row1 = row0 + 8;

    for (int kt = 0; kt < nkt; kt++) {
        const int kbase = kt * BK;
        CP_WAIT0();
        __syncthreads();
        if (kt + 1 < nkt) {
            uint32_t dst = sb + ((kt + 1) & 1) * BUFB + tid * 16;
            const uint32_t o2 = (uint32_t)(kt + 1) * 1024 + (uint32_t)tid * 2;
            #pragma unroll
            for (int i = 0; i < 4; i++) {
                cpa16(dst + P_KH + i * 2048, pKH + o2 + i * 256);
                cpa16(dst + P_KL + i * 2048, pKL + o2 + i * 256);
                cpa16(dst + P_V  + i * 2048, pV  + o2 + i * 256);
            }
            CP_COMMIT();
        }
        const uint32_t KB = sb + (kt & 1) * BUFB;
        const uint32_t fo = (uint32_t)(la * 32 + lb * 8);

        // ---------- S = Q @ K^T: pass-major, same-c distance 8 ----------
        float c[8][4];
        #pragma unroll
        for (int j = 0; j < 8; j++)
            #pragma unroll
            for (int i = 0; i < 4; i++) c[j][i] = 0.f;

        #pragma unroll
        for (int t = 0; t < 4; t++) {
            uint32_t bh[8][2], bl[8][2];
            #pragma unroll
            for (int j = 0; j < 8; j++)
                lds64(bh[j][0], bh[j][1], KB + P_KH + (uint32_t)j * 1024 + (uint32_t)t * 256 + fo);
            #pragma unroll
            for (int j = 0; j < 8; j++)
                mma_f16(c[j], Qhi[t], bh[j][0], bh[j][1]);
            #pragma unroll
            for (int j = 0; j < 8; j++)
                lds64(bl[j][0], bl[j][1], KB + P_KL + (uint32_t)j * 1024 + (uint32_t)t * 256 + fo);
            #pragma unroll
            for (int j = 0; j < 8; j++)
                mma_f16(c[j], Qlo[t], bh[j][0], bh[j][1]);
            #pragma unroll
            for (int j = 0; j < 8; j++)
                mma_f16(c[j], Qhi[t], bl[j][0], bl[j][1]);
        }

        // ---------- mask (only diagonal tile) ----------
        if (kbase + BK > row0) {
            #pragma unroll
            for (int j = 0; j < 8; j++) {
                int col = kbase + 8 * j + lb * 2;
                if (col     > row0) c[j][0] = -1e30f;
                if (col + 1 > row0) c[j][1] = -1e30f;
                if (col     > row1) c[j][2] = -1e30f;
                if (col + 1 > row1) c[j][3] = -1e30f;
            }
        }

        // ---------- running max update + ls rescale ----------
        float scl[2];
        #pragma unroll
        for (int rh = 0; rh < 2; rh++) {
            float mx = -1e30f;
            #pragma unroll
            for (int j = 0; j < 8; j++)
                mx = fmaxf(mx, fmaxf(c[j][2*rh], c[j][2*rh+1]));
            mx = fmaxf(mx, __shfl_xor_sync(0xffffffffu, mx, 1));
            mx = fmaxf(mx, __shfl_xor_sync(0xffffffffu, mx, 2));
            float mn = fmaxf(m_[rh], mx);
            float s = ex2f(m_[rh] - mn);
            m_[rh] = mn;
            scl[rh] = s;
            ls[rh] *= s;
        }
        bool need = (scl[0] != 1.f) | (scl[1] != 1.f);
        if (__any_sync(0xffffffffu, need)) {
            #pragma unroll
            for (int j = 0; j < 8; j++) {
                o[j][0] *= scl[0]; o[j][1] *= scl[0];
                o[j][2] *= scl[1]; o[j][3] *= scl[1];
            }
        }

        // ---------- exp2 + pack P (single fp16 plane, in [0,1]) ----------
        uint32_t Phi[4][4];
        #pragma unroll
        for (int j = 0; j < 8; j++) {
            float p0 = ex2f(c[j][0] - m_[0]);
            float p1 = ex2f(c[j][1] - m_[0]);
            float p2 = ex2f(c[j][2] - m_[1]);
            float p3 = ex2f(c[j][3] - m_[1]);
            ls[0] += p0 + p1; ls[1] += p2 + p3;
            int t = j >> 1, off = (j & 1) ? 2 : 0;
            Phi[t][off]     = pack_h(p0, p1);
            Phi[t][off + 1] = pack_h(p2, p3);
        }

        // ---------- O += P @ V: full-j per t, same-o distance 8 ----------
        #pragma unroll
        for (int t = 0; t < 4; t++) {
            uint32_t bv[8][2];
            #pragma unroll
            for (int j = 0; j < 8; j++)
                lds64(bv[j][0], bv[j][1], KB + P_V + (uint32_t)t * 2048 + (uint32_t)j * 256 + fo);
            #pragma unroll
            for (int j = 0; j < 8; j++)
                mma_f16(o[j], Phi[t], bv[j][0], bv[j][1]);
        }
    }

    // ---------- normalize + store ----------
    #pragma unroll
    for (int i = 0; i < 2; i++) {
        ls[i] += __shfl_xor_sync(0xffffffffu, ls[i], 1);
        ls[i] += __shfl_xor_sync(0xffffffffu, ls[i], 2);
    }
    {
        float inv0 = 1.0f / ls[0], inv1 = 1.0f / ls[1];
        const int lq0 = n * C_ + row0, lq1 = n * C_ + row1;
        float* g0 = out + (((long)b * L_ + lq0) * H_ + h) * D_;
        float* g1 = out + (((long)b * L_ + lq1) * H_ + h) * D_;
        #pragma unroll
        for (int j = 0; j < 8; j++) {
            int d = 8 * j + lb * 2;
            *(float2*)(g0 + d) = make_float2(o[j][0] * inv0, o[j][1] * inv0);
            *(float2*)(g1 + d) = make_float2(o[j][2] * inv1, o[j][3] * inv1);
        }
    }
}

extern "C" void kernel_launch(void* const* d_in, const int* in_sizes, int n_in,
                              void* d_out, int out_size) {
    const float* q = (const float*)d_in[0];
    const float* k = (const float*)d_in[1];
    const float* v = (const float*)d_in[2];
    const int* st  = (const int*)d_in[3];
    float* out     = (float*)d_out;

    cudaFuncSetAttribute(attn_k, cudaFuncAttributeMaxDynamicSharedMemorySize, 2 * BUFB);

    invf_k<<<1, 32>>>();
    rope_table_k<<<(L_ * 32 + 255) / 256, 256>>>(st);
    prep_kv<<<8192 + 4096, 256>>>(k, v);
    attn_k<<<dim3(16, (L_ / C_) * H_, B_), 128, 2 * BUFB>>>(q, out);
}